// round 14
// baseline (speedup 1.0000x reference)
#include <cuda_runtime.h>
#include <cstdint>
#include <cstddef>

// Problem constants
#define B_Q   1024
#define D_DIM 256
#define N_TR  200000
#define N_CLS 1000
#define K_TOP 20
#define TEMP  20.0f

// GEMM tiling
#define NT_TILE 128                 // train rows per CTA
#define MT_TILE 64                  // query rows per m-block
#define PITCH   260                 // 256 + 4 pad -> conflict-free LDS.128
#define SMEM_BYTES ((NT_TILE + MT_TILE) * PITCH * 4)
#define NBLK  ((N_TR + NT_TILE - 1) / NT_TILE)   // 1563 n-blocks

// ---------------- device scratch (statically allocated; no cudaMalloc) ------
__device__ __align__(16) float g_q[B_Q * D_DIM];          // normalized queries
__device__ float g_txinv[N_TR];                            // 1/max(||t||,eps)
__device__ __align__(16) float g_sim[(size_t)B_Q * N_TR];  // 819 MB sim matrix
__device__ float g_blkmax[(size_t)B_Q * NBLK];             // per-row block maxes
__device__ float g_topv[B_Q * K_TOP];
__device__ int   g_topi[B_Q * K_TOP];

// ---------------- packed f32x2 FMA ------------------------------------------
__device__ __forceinline__ void ffma2(unsigned long long& c,
                                      unsigned long long a,
                                      unsigned long long b) {
    asm("fma.rn.f32x2 %0, %1, %2, %0;" : "+l"(c) : "l"(a), "l"(b));
}

// ---------------- kernel 1: q = l2norm((x-mean)*inv_std) --------------------
__global__ void k_qnorm(const float* __restrict__ x,
                        const float* __restrict__ mean,
                        const float* __restrict__ inv_std) {
    __shared__ float red[8];
    __shared__ float s_den;
    const int b = blockIdx.x, d = threadIdx.x;
    float t = (x[b * D_DIM + d] - mean[d]) * inv_std[d];
    float ss = t * t;
    #pragma unroll
    for (int o = 16; o; o >>= 1) ss += __shfl_xor_sync(0xffffffffu, ss, o);
    if ((d & 31) == 0) red[d >> 5] = ss;
    __syncthreads();
    if (d == 0) {
        float s = 0.f;
        #pragma unroll
        for (int w = 0; w < 8; w++) s += red[w];
        s_den = fmaxf(sqrtf(s), 1e-8f);
    }
    __syncthreads();
    g_q[b * D_DIM + d] = t / s_den;
}

// ---------------- kernel 2: per-row inverse L2 norm of train bank -----------
__global__ void k_txinv(const float* __restrict__ tx) {
    const int row  = blockIdx.x * 8 + (threadIdx.x >> 5);
    const int lane = threadIdx.x & 31;
    const float4* p = (const float4*)(tx + (size_t)row * D_DIM);
    float4 a = p[lane * 2];
    float4 c = p[lane * 2 + 1];
    float ss = a.x*a.x + a.y*a.y + a.z*a.z + a.w*a.w
             + c.x*c.x + c.y*c.y + c.z*c.z + c.w*c.w;
    #pragma unroll
    for (int o = 16; o; o >>= 1) ss += __shfl_xor_sync(0xffffffffu, ss, o);
    if (lane == 0) g_txinv[row] = 1.0f / fmaxf(sqrtf(ss), 1e-8f);
}

// ---------------- kernel 3: sim = q @ txn^T (fp32 via packed f32x2) ---------
// Epilogue additionally emits the per-(row, n-block) max into g_blkmax for
// the pruned top-k pass. Padded lanes (n >= N_TR) excluded from the max.
__global__ void __launch_bounds__(256, 1) k_gemm(const float* __restrict__ tx) {
    extern __shared__ float sm[];
    float* txs = sm;                       // NT_TILE x PITCH
    float* qs  = sm + NT_TILE * PITCH;     // MT_TILE x PITCH

    const int n0  = blockIdx.x * NT_TILE;
    const int tid = threadIdx.x;

    // Load tx tile once, folding L2 normalization; zero-pad past N_TR.
    for (int idx = tid; idx < NT_TILE * 64; idx += 256) {
        const int r = idx >> 6, c4 = idx & 63;
        const int n = n0 + r;
        float4 v = make_float4(0.f, 0.f, 0.f, 0.f);
        if (n < N_TR) {
            v = __ldg((const float4*)(tx + (size_t)n * D_DIM) + c4);
            const float s = g_txinv[n];
            v.x *= s; v.y *= s; v.z *= s; v.w *= s;
        }
        *(float4*)(txs + r * PITCH + c4 * 4) = v;
    }
    __syncthreads();

    const int nt = tid & 31;   // n-group: warp lanes span all 32
    const int mt = tid >> 5;   // m-group: uniform within a warp (q broadcast)

    for (int mb = 0; mb < B_Q / MT_TILE; mb++) {
        for (int idx = tid; idx < MT_TILE * 64; idx += 256) {
            const int r = idx >> 6, c4 = idx & 63;
            *(float4*)(qs + r * PITCH + c4 * 4) =
                ((const float4*)(g_q + (mb * MT_TILE + r) * D_DIM))[c4];
        }
        __syncthreads();

        unsigned long long acc[8][4];
        #pragma unroll
        for (int i = 0; i < 8; i++)
            #pragma unroll
            for (int j = 0; j < 4; j++) acc[i][j] = 0ULL;  // bits(+0,+0)

        #pragma unroll 2
        for (int k4 = 0; k4 < 64; k4++) {
            ulonglong2 bf[4], af[8];
            #pragma unroll
            for (int j = 0; j < 4; j++)
                bf[j] = *(const ulonglong2*)(txs + (nt + 32 * j) * PITCH + k4 * 4);
            #pragma unroll
            for (int i = 0; i < 8; i++)
                af[i] = *(const ulonglong2*)(qs + (mt * 8 + i) * PITCH + k4 * 4);
            #pragma unroll
            for (int i = 0; i < 8; i++)
                #pragma unroll
                for (int j = 0; j < 4; j++)
                    ffma2(acc[i][j], af[i].x, bf[j].x);
            #pragma unroll
            for (int i = 0; i < 8; i++)
                #pragma unroll
                for (int j = 0; j < 4; j++)
                    ffma2(acc[i][j], af[i].y, bf[j].y);
        }

        #pragma unroll
        for (int i = 0; i < 8; i++) {
            const int m = mb * MT_TILE + mt * 8 + i;
            float* orow = g_sim + (size_t)m * N_TR + n0;
            float vmax = -2e30f;
            #pragma unroll
            for (int j = 0; j < 4; j++) {
                const int n = nt + 32 * j;
                if (n0 + n < N_TR) {
                    float lo, hi;
                    asm("mov.b64 {%0,%1}, %2;" : "=f"(lo), "=f"(hi) : "l"(acc[i][j]));
                    const float v = lo + hi;    // even-k + odd-k partial sums
                    orow[n] = v;
                    vmax = fmaxf(vmax, v);
                }
            }
            // warp-wide max over the 128 n-values of this row's block
            #pragma unroll
            for (int o = 16; o; o >>= 1)
                vmax = fmaxf(vmax, __shfl_xor_sync(0xffffffffu, vmax, o));
            if (nt == 0)
                g_blkmax[(size_t)m * NBLK + blockIdx.x] = vmax;
        }
        __syncthreads();
    }
}

// ---------------- top-k helpers ----------------------------------------------
__device__ __forceinline__ void tk_rescan(const float* sv, int base,
                                          float& vmin, int& pmin) {
    float m = sv[base]; int p = base;
    #pragma unroll
    for (int j = 1; j < K_TOP; j++) {
        const float w = sv[base + j];
        if (w < m) { m = w; p = base + j; }
    }
    vmin = m; pmin = p;
}

// Exact top-20 merge across 256 per-thread lists in shared memory.
// WRITE_OUT: write (value, si[]) pairs to g_topv/g_topi for row b.
// Always records the round-19 (20th largest) value into *tau_out (tid 0).
template <bool WRITE_OUT>
__device__ void tk_merge(float* sv, int* si, float* rv, int* rp,
                         int tid, int b, float* tau_out) {
    const int lane = tid & 31, wid = tid >> 5, base = tid * K_TOP;
    for (int r = 0; r < K_TOP; r++) {
        float lv = -3.0f; int lp = base;
        #pragma unroll
        for (int j = 0; j < K_TOP; j++) {
            const float w = sv[base + j];
            if (w > lv) { lv = w; lp = base + j; }
        }
        #pragma unroll
        for (int o = 16; o > 0; o >>= 1) {
            const float ov = __shfl_down_sync(0xffffffffu, lv, o);
            const int   op = __shfl_down_sync(0xffffffffu, lp, o);
            if (ov > lv) { lv = ov; lp = op; }
        }
        if (lane == 0) { rv[wid] = lv; rp[wid] = lp; }
        __syncthreads();
        if (tid == 0) {
            float gv = rv[0]; int gp = rp[0];
            #pragma unroll
            for (int w = 1; w < 8; w++)
                if (rv[w] > gv) { gv = rv[w]; gp = rp[w]; }
            if (WRITE_OUT) {
                g_topv[b * K_TOP + r] = gv;
                g_topi[b * K_TOP + r] = si[gp];
            }
            if (r == K_TOP - 1) *tau_out = gv;
            sv[gp] = -3.0f;   // consume
        }
        __syncthreads();
    }
}

// ---------------- kernel 4: pruned per-row top-20 ----------------------------
// Phase 1: exact top-20 of the 1563 block maxes -> tau (20th largest).
// Since each blockmax is an actual element, true-20th-element >= tau.
// Phase 2: scan ONLY blocks with blockmax >= tau (superset-safe, tie-proof:
// any element e >= true-20th has blockmax >= e >= tau). ~20 blocks x 128.
#define CAND_MAX 96
__global__ void __launch_bounds__(256) k_topk() {
    __shared__ float sv[256 * K_TOP];
    __shared__ int   si[256 * K_TOP];
    __shared__ float rv[8];
    __shared__ int   rp[8];
    __shared__ float s_tau;
    __shared__ int   s_cand[CAND_MAX];
    __shared__ int   s_cnt;
    const int b    = blockIdx.x;
    const int tid  = threadIdx.x;
    const int base = tid * K_TOP;

    // ---- Phase 1: tau from block maxes ----
    #pragma unroll
    for (int j = 0; j < K_TOP; j++) { sv[base + j] = -2.0f; si[base + j] = 0; }
    float vmin = -2.0f; int pmin = base;

    const float* bm = g_blkmax + (size_t)b * NBLK;
    for (int i = tid; i < NBLK; i += 256) {
        const float v = bm[i];
        if (v > vmin) { sv[pmin] = v; si[pmin] = i; tk_rescan(sv, base, vmin, pmin); }
    }
    if (tid == 0) s_cnt = 0;
    __syncthreads();
    tk_merge<false>(sv, si, rv, rp, tid, b, &s_tau);

    // ---- Phase 2: compact candidate blocks, gather, exact top-20 ----
    const float tau = s_tau;
    for (int i = tid; i < NBLK; i += 256) {
        if (bm[i] >= tau) {
            const int p = atomicAdd(&s_cnt, 1);
            if (p < CAND_MAX) s_cand[p] = i;
        }
    }
    #pragma unroll
    for (int j = 0; j < K_TOP; j++) { sv[base + j] = -2.0f; si[base + j] = 0; }
    vmin = -2.0f; pmin = base;
    __syncthreads();

    const int cnt = min(s_cnt, CAND_MAX);
    const float* row = g_sim + (size_t)b * N_TR;
    for (int idx = tid; idx < cnt * NT_TILE; idx += 256) {
        const int blk = s_cand[idx >> 7];
        const int n   = blk * NT_TILE + (idx & 127);
        if (n < N_TR) {
            const float v = __ldg(row + n);
            if (v > vmin) { sv[pmin] = v; si[pmin] = n; tk_rescan(sv, base, vmin, pmin); }
        }
    }
    __syncthreads();
    tk_merge<true>(sv, si, rv, rp, tid, b, &s_tau);
}

// ---------------- kernel 5: zero row + softmax-weighted label scatter -------
// train_y arrives as int32 (jax x64-disabled downcasts the reference's int64).
__global__ void k_out(const int* __restrict__ ty, float* __restrict__ out) {
    const int b = blockIdx.x;
    float* row = out + b * N_CLS;
    for (int i = threadIdx.x; i < N_CLS; i += 256) row[i] = 0.0f;
    __syncthreads();
    if (threadIdx.x < 32) {
        const int j = threadIdx.x;
        const float v = (j < K_TOP) ? g_topv[b * K_TOP + j] : -1e30f;
        float mx = v;
        #pragma unroll
        for (int o = 16; o; o >>= 1) mx = fmaxf(mx, __shfl_xor_sync(0xffffffffu, mx, o));
        const float e = (j < K_TOP) ? expf((v - mx) * TEMP) : 0.0f;
        float s = e;
        #pragma unroll
        for (int o = 16; o; o >>= 1) s += __shfl_xor_sync(0xffffffffu, s, o);
        if (j < K_TOP) {
            const int lab = ty[g_topi[b * K_TOP + j]];
            atomicAdd(row + lab, e / s);
        }
    }
}

// ---------------- launch -----------------------------------------------------
extern "C" void kernel_launch(void* const* d_in, const int* in_sizes, int n_in,
                              void* d_out, int out_size) {
    (void)in_sizes; (void)n_in; (void)out_size;
    const float* x       = (const float*)d_in[0];
    const float* mean    = (const float*)d_in[1];
    const float* inv_std = (const float*)d_in[2];
    const float* tx      = (const float*)d_in[3];
    const int*   ty      = (const int*)d_in[4];
    float* out = (float*)d_out;

    cudaFuncSetAttribute(k_gemm, cudaFuncAttributeMaxDynamicSharedMemorySize,
                         SMEM_BYTES);

    k_qnorm<<<B_Q, 256>>>(x, mean, inv_std);
    k_txinv<<<N_TR / 8, 256>>>(tx);
    k_gemm<<<NBLK, 256, SMEM_BYTES>>>(tx);
    k_topk<<<B_Q, 256>>>();
    k_out<<<B_Q, 256>>>(ty, out);
}

// round 17
// speedup vs baseline: 4.5275x; 4.5275x over previous
#include <cuda_runtime.h>
#include <cuda_bf16.h>
#include <cstdint>
#include <cstddef>

// Problem constants
#define B_Q   1024
#define D_DIM 256
#define N_TR  200000
#define N_CLS 1000
#define K_TOP 20
#define TEMP  20.0f

// bf16 mma GEMM tiling: CTA 128m x 64n, K=256 resident. 8 warps, 32x32 each.
#define TMM    128
#define TNN    64
#define NBLK   (N_TR / TNN)            // 3125 exact
#define APITCH 264                      // bf16 elems per smem row (528B, bank+4/row)
#define A_SM_BYTES (TMM * APITCH * 2)   // 67584
#define B_SM_BYTES (TNN * APITCH * 2)   // 33792
#define GEMM_SMEM  (A_SM_BYTES + B_SM_BYTES)  // 101376 -> 2 CTAs/SM

// candidate filter margin: covers mma noise (~38 sigma) + bf16 store rounding
#define MARGIN 6.0e-3f
#define BLK_MAX  192
#define CAND_MAX 512

// ---------------- device scratch ---------------------------------------------
__device__ __align__(16) float          g_q[B_Q * D_DIM];      // exact normalized queries
__device__ __align__(16) __nv_bfloat16  g_qb[B_Q * D_DIM];     // bf16 normalized queries
__device__ __align__(16) __nv_bfloat16  g_tb[(size_t)N_TR * D_DIM];  // bf16 normalized train
__device__ float g_txinv[N_TR];                                 // 1/max(||t||,eps)
__device__ __align__(16) __nv_bfloat16  g_simb[(size_t)B_Q * N_TR];  // 410MB approx sims
__device__ float g_blkmax[(size_t)B_Q * NBLK];
__device__ float g_topv[B_Q * K_TOP];
__device__ int   g_topi[B_Q * K_TOP];

// ---------------- PTX helpers -------------------------------------------------
__device__ __forceinline__ uint32_t smem_u32(const void* p) {
    uint32_t a;
    asm("{ .reg .u64 t; cvta.to.shared.u64 t, %1; cvt.u32.u64 %0, t; }"
        : "=r"(a) : "l"(p));
    return a;
}
__device__ __forceinline__ void ldsm_x4(uint32_t* r, uint32_t addr) {
    asm volatile("ldmatrix.sync.aligned.m8n8.x4.shared.b16 {%0,%1,%2,%3}, [%4];"
                 : "=r"(r[0]), "=r"(r[1]), "=r"(r[2]), "=r"(r[3]) : "r"(addr));
}
__device__ __forceinline__ void mma_bf16(float* d, const uint32_t* a,
                                         const uint32_t* b) {
    asm volatile(
        "mma.sync.aligned.m16n8k16.row.col.f32.bf16.bf16.f32 "
        "{%0,%1,%2,%3}, {%4,%5,%6,%7}, {%8,%9}, {%0,%1,%2,%3};"
        : "+f"(d[0]), "+f"(d[1]), "+f"(d[2]), "+f"(d[3])
        : "r"(a[0]), "r"(a[1]), "r"(a[2]), "r"(a[3]), "r"(b[0]), "r"(b[1]));
}
__device__ __forceinline__ uint32_t pack_bf16x2(float lo, float hi) {
    uint32_t r;
    asm("cvt.rn.bf16x2.f32 %0, %1, %2;" : "=r"(r) : "f"(hi), "f"(lo));
    return r;
}

// ---------------- kernel 1: q -> exact fp32 + bf16 normalized ----------------
__global__ void k_qnorm(const float* __restrict__ x,
                        const float* __restrict__ mean,
                        const float* __restrict__ inv_std) {
    __shared__ float red[8];
    __shared__ float s_den;
    const int b = blockIdx.x, d = threadIdx.x;
    float t = (x[b * D_DIM + d] - mean[d]) * inv_std[d];
    float ss = t * t;
    #pragma unroll
    for (int o = 16; o; o >>= 1) ss += __shfl_xor_sync(0xffffffffu, ss, o);
    if ((d & 31) == 0) red[d >> 5] = ss;
    __syncthreads();
    if (d == 0) {
        float s = 0.f;
        #pragma unroll
        for (int w = 0; w < 8; w++) s += red[w];
        s_den = fmaxf(sqrtf(s), 1e-8f);
    }
    __syncthreads();
    const float v = t / s_den;
    g_q[b * D_DIM + d]  = v;
    g_qb[b * D_DIM + d] = __float2bfloat16(v);
}

// ---------------- kernel 2: train rows -> inv-norm + bf16 normalized ---------
__global__ void k_prep(const float* __restrict__ tx) {
    const int row  = blockIdx.x * 8 + (threadIdx.x >> 5);
    const int lane = threadIdx.x & 31;
    const float4* p = (const float4*)(tx + (size_t)row * D_DIM);
    float4 a = p[lane * 2];
    float4 c = p[lane * 2 + 1];
    float ss = a.x*a.x + a.y*a.y + a.z*a.z + a.w*a.w
             + c.x*c.x + c.y*c.y + c.z*c.z + c.w*c.w;
    #pragma unroll
    for (int o = 16; o; o >>= 1) ss += __shfl_xor_sync(0xffffffffu, ss, o);
    const float inv = 1.0f / fmaxf(sqrtf(ss), 1e-8f);
    if (lane == 0) g_txinv[row] = inv;

    const float v[8] = { a.x*inv, a.y*inv, a.z*inv, a.w*inv,
                         c.x*inv, c.y*inv, c.z*inv, c.w*inv };
    uint4 pk;
    pk.x = pack_bf16x2(v[0], v[1]);
    pk.y = pack_bf16x2(v[2], v[3]);
    pk.z = pack_bf16x2(v[4], v[5]);
    pk.w = pack_bf16x2(v[6], v[7]);
    ((uint4*)(g_tb + (size_t)row * D_DIM))[lane] = pk;
}

// ---------------- kernel 3: bf16 mma.sync GEMM, 128x64 per CTA ----------------
// A = queries [128 x 256], B = train rows [64 x 256] (both k-contiguous bf16).
// Stores bf16 sims + per-(row, 64-wide n-block) fp32 max.
__global__ void __launch_bounds__(256, 2) k_gemm_mma() {
    extern __shared__ __align__(16) char sm[];
    __nv_bfloat16* As = (__nv_bfloat16*)sm;
    __nv_bfloat16* Bs = (__nv_bfloat16*)(sm + A_SM_BYTES);

    const int tid  = threadIdx.x;
    const int lane = tid & 31, wid = tid >> 5;
    const int m0 = blockIdx.x * TMM;
    const int n0 = blockIdx.y * TNN;

    // Load A tile (64KB) and B tile (32KB), 16B per thread per iter.
    #pragma unroll
    for (int it = 0; it < 16; it++) {
        const int idx = tid + it * 256, r = idx >> 5, c = idx & 31;
        *(uint4*)(As + r * APITCH + c * 8) =
            ((const uint4*)(g_qb + (size_t)(m0 + r) * D_DIM))[c];
    }
    #pragma unroll
    for (int it = 0; it < 8; it++) {
        const int idx = tid + it * 256, r = idx >> 5, c = idx & 31;
        *(uint4*)(Bs + r * APITCH + c * 8) =
            ((const uint4*)(g_tb + (size_t)(n0 + r) * D_DIM))[c];
    }
    __syncthreads();

    const int warpm = wid >> 1, warpn = wid & 1;

    // ldmatrix lane base addresses (bytes), k-step adds 32B.
    uint32_t a_base[2], b_base[2];
    {
        const uint32_t smA = smem_u32(As), smB = smem_u32(Bs);
        #pragma unroll
        for (int mt = 0; mt < 2; mt++) {
            const int row = warpm * 32 + mt * 16 + (lane & 7) + ((lane & 8) ? 8 : 0);
            a_base[mt] = smA + row * (APITCH * 2) + ((lane & 16) ? 16 : 0);
        }
        #pragma unroll
        for (int p = 0; p < 2; p++) {
            const int row = warpn * 32 + p * 16 + ((lane & 16) ? 8 : 0) + (lane & 7);
            b_base[p] = smB + row * (APITCH * 2) + ((lane & 8) ? 16 : 0);
        }
    }

    float acc[2][4][4];
    #pragma unroll
    for (int mt = 0; mt < 2; mt++)
        #pragma unroll
        for (int nt = 0; nt < 4; nt++)
            #pragma unroll
            for (int e = 0; e < 4; e++) acc[mt][nt][e] = 0.0f;

    #pragma unroll
    for (int ks = 0; ks < 16; ks++) {
        uint32_t af[2][4], bfr[2][4];
        ldsm_x4(af[0],  a_base[0] + ks * 32);
        ldsm_x4(af[1],  a_base[1] + ks * 32);
        ldsm_x4(bfr[0], b_base[0] + ks * 32);
        ldsm_x4(bfr[1], b_base[1] + ks * 32);
        #pragma unroll
        for (int mt = 0; mt < 2; mt++)
            #pragma unroll
            for (int nt = 0; nt < 4; nt++)
                mma_bf16(acc[mt][nt], af[mt], &bfr[nt >> 1][(nt & 1) * 2]);
    }
    __syncthreads();   // all smem reads done; safe to overlay rowmax below

    // Epilogue: bf16 sim stores + per-row max.
    const int g = lane >> 2, q4 = lane & 3;
    float* rm = (float*)sm;   // [2][128]
    #pragma unroll
    for (int mt = 0; mt < 2; mt++) {
        #pragma unroll
        for (int hf = 0; hf < 2; hf++) {
            const int rloc = warpm * 32 + mt * 16 + hf * 8 + g;
            __nv_bfloat16* srow = g_simb + (size_t)(m0 + rloc) * N_TR + n0;
            float vr = -3e30f;
            #pragma unroll
            for (int nt = 0; nt < 4; nt++) {
                const float v0 = acc[mt][nt][hf * 2];
                const float v1 = acc[mt][nt][hf * 2 + 1];
                const int col = warpn * 32 + nt * 8 + 2 * q4;
                *(uint32_t*)(srow + col) = pack_bf16x2(v0, v1);
                vr = fmaxf(vr, fmaxf(v0, v1));
            }
            vr = fmaxf(vr, __shfl_xor_sync(0xffffffffu, vr, 1));
            vr = fmaxf(vr, __shfl_xor_sync(0xffffffffu, vr, 2));
            if (q4 == 0) rm[warpn * 128 + rloc] = vr;
        }
    }
    __syncthreads();
    if (tid < 128)
        g_blkmax[(size_t)(m0 + tid) * NBLK + blockIdx.y] =
            fmaxf(rm[tid], rm[128 + tid]);
}

// ---------------- top-k helpers ----------------------------------------------
__device__ __forceinline__ void tk_rescan(const float* sv, int base,
                                          float& vmin, int& pmin) {
    float m = sv[base]; int p = base;
    #pragma unroll
    for (int j = 1; j < K_TOP; j++) {
        const float w = sv[base + j];
        if (w < m) { m = w; p = base + j; }
    }
    vmin = m; pmin = p;
}

template <bool WRITE_OUT>
__device__ void tk_merge(float* sv, int* si, float* rv, int* rp,
                         int tid, int b, float* tau_out) {
    const int lane = tid & 31, wid = tid >> 5, base = tid * K_TOP;
    for (int r = 0; r < K_TOP; r++) {
        float lv = -3.0f; int lp = base;
        #pragma unroll
        for (int j = 0; j < K_TOP; j++) {
            const float w = sv[base + j];
            if (w > lv) { lv = w; lp = base + j; }
        }
        #pragma unroll
        for (int o = 16; o > 0; o >>= 1) {
            const float ov = __shfl_down_sync(0xffffffffu, lv, o);
            const int   op = __shfl_down_sync(0xffffffffu, lp, o);
            if (ov > lv) { lv = ov; lp = op; }
        }
        if (lane == 0) { rv[wid] = lv; rp[wid] = lp; }
        __syncthreads();
        if (tid == 0) {
            float gv = rv[0]; int gp = rp[0];
            #pragma unroll
            for (int w = 1; w < 8; w++)
                if (rv[w] > gv) { gv = rv[w]; gp = rp[w]; }
            if (WRITE_OUT) {
                g_topv[b * K_TOP + r] = gv;
                g_topi[b * K_TOP + r] = si[gp];
            }
            if (r == K_TOP - 1) *tau_out = gv;
            sv[gp] = -3.0f;
        }
        __syncthreads();
    }
}

// ---------------- kernel 4: filtered top-20 + exact fp32 rescore --------------
__global__ void __launch_bounds__(256) k_topk(const float* __restrict__ tx) {
    __shared__ float sv[256 * K_TOP];
    __shared__ int   si[256 * K_TOP];
    __shared__ float rv[8];
    __shared__ int   rp[8];
    __shared__ float s_tau;
    __shared__ int   s_blk[BLK_MAX];
    __shared__ int   s_nb;
    __shared__ int   cand_n[CAND_MAX];
    __shared__ float cand_v[CAND_MAX];
    __shared__ int   s_nc;
    __shared__ float qrow[D_DIM];
    const int b    = blockIdx.x;
    const int tid  = threadIdx.x;
    const int base = tid * K_TOP;
    const int lane = tid & 31, wid = tid >> 5;

    // Phase 1: exact top-20 of block maxes -> tau (20th largest blockmax).
    #pragma unroll
    for (int j = 0; j < K_TOP; j++) { sv[base + j] = -2.0f; si[base + j] = 0; }
    float vmin = -2.0f; int pmin = base;
    const float* bm = g_blkmax + (size_t)b * NBLK;
    for (int i = tid; i < NBLK; i += 256) {
        const float v = bm[i];
        if (v > vmin) { sv[pmin] = v; si[pmin] = i; tk_rescan(sv, base, vmin, pmin); }
    }
    if (tid == 0) { s_nb = 0; s_nc = 0; }
    if (tid < D_DIM) qrow[tid] = g_q[b * D_DIM + tid];
    __syncthreads();
    tk_merge<false>(sv, si, rv, rp, tid, b, &s_tau);

    // Phase 2: candidate blocks, then candidate elements (approx >= tau-margin).
    const float thr = s_tau - MARGIN;
    for (int i = tid; i < NBLK; i += 256) {
        if (bm[i] >= thr) {
            const int p = atomicAdd(&s_nb, 1);
            if (p < BLK_MAX) s_blk[p] = i;
        }
    }
    __syncthreads();
    const int nb = min(s_nb, BLK_MAX);
    const __nv_bfloat16* srow = g_simb + (size_t)b * N_TR;
    for (int idx = tid; idx < nb * TNN; idx += 256) {
        const int n = s_blk[idx >> 6] * TNN + (idx & 63);
        const float v = __bfloat162float(srow[n]);
        if (v >= thr) {
            const int p = atomicAdd(&s_nc, 1);
            if (p < CAND_MAX) cand_n[p] = n;
        }
    }
    __syncthreads();

    // Exact fp32 rescore: one warp per candidate (8 floats per lane).
    const int nc = min(s_nc, CAND_MAX);
    for (int c = wid; c < nc; c += 8) {
        const int n = cand_n[c];
        const float4* tp = (const float4*)(tx + (size_t)n * D_DIM);
        const float4 t0 = tp[lane * 2];
        const float4 t1 = tp[lane * 2 + 1];
        const float* qp = qrow + lane * 8;
        float d = t0.x*qp[0] + t0.y*qp[1] + t0.z*qp[2] + t0.w*qp[3]
                + t1.x*qp[4] + t1.y*qp[5] + t1.z*qp[6] + t1.w*qp[7];
        #pragma unroll
        for (int o = 16; o; o >>= 1) d += __shfl_xor_sync(0xffffffffu, d, o);
        if (lane == 0) cand_v[c] = d * g_txinv[n];
    }
    __syncthreads();

    // Final exact top-20 over the rescored candidates.
    #pragma unroll
    for (int j = 0; j < K_TOP; j++) { sv[base + j] = -2.0f; si[base + j] = 0; }
    vmin = -2.0f; pmin = base;
    for (int c = tid; c < nc; c += 256) {
        const float v = cand_v[c];
        if (v > vmin) { sv[pmin] = v; si[pmin] = cand_n[c]; tk_rescan(sv, base, vmin, pmin); }
    }
    __syncthreads();
    tk_merge<true>(sv, si, rv, rp, tid, b, &s_tau);
}

// ---------------- kernel 5: softmax-weighted label scatter -------------------
__global__ void k_out(const int* __restrict__ ty, float* __restrict__ out) {
    const int b = blockIdx.x;
    float* row = out + b * N_CLS;
    for (int i = threadIdx.x; i < N_CLS; i += 256) row[i] = 0.0f;
    __syncthreads();
    if (threadIdx.x < 32) {
        const int j = threadIdx.x;
        const float v = (j < K_TOP) ? g_topv[b * K_TOP + j] : -1e30f;
        float mx = v;
        #pragma unroll
        for (int o = 16; o; o >>= 1) mx = fmaxf(mx, __shfl_xor_sync(0xffffffffu, mx, o));
        const float e = (j < K_TOP) ? expf((v - mx) * TEMP) : 0.0f;
        float s = e;
        #pragma unroll
        for (int o = 16; o; o >>= 1) s += __shfl_xor_sync(0xffffffffu, s, o);
        if (j < K_TOP) {
            const int lab = ty[g_topi[b * K_TOP + j]];
            atomicAdd(row + lab, e / s);
        }
    }
}

// ---------------- launch -----------------------------------------------------
extern "C" void kernel_launch(void* const* d_in, const int* in_sizes, int n_in,
                              void* d_out, int out_size) {
    (void)in_sizes; (void)n_in; (void)out_size;
    const float* x       = (const float*)d_in[0];
    const float* mean    = (const float*)d_in[1];
    const float* inv_std = (const float*)d_in[2];
    const float* tx      = (const float*)d_in[3];
    const int*   ty      = (const int*)d_in[4];
    float* out = (float*)d_out;

    cudaFuncSetAttribute(k_gemm_mma, cudaFuncAttributeMaxDynamicSharedMemorySize,
                         GEMM_SMEM);

    k_qnorm<<<B_Q, 256>>>(x, mean, inv_std);
    k_prep<<<N_TR / 8, 256>>>(tx);
    k_gemm_mma<<<dim3(B_Q / TMM, NBLK), 256, GEMM_SMEM>>>();
    k_topk<<<B_Q, 256>>>(tx);
    k_out<<<B_Q, 256>>>(ty, out);
}